// round 1
// baseline (speedup 1.0000x reference)
#include <cuda_runtime.h>

#define BC      128          // B*C = 8*16
#define B_DIM   8
#define C_DIM   16
#define HW      147456       // 384*384
#define HW4     36864        // HW/4
#define SPLIT   12
#define CHUNK4  (HW4 / SPLIT)   // 3072
#define NTHREADS 256

#define ALPHA   0.05f
#define SMOOTH  1e-6f

// scratch: [BC * SPLIT][5] partials: {sum_d2t, sum_d2, sum_t, max_t, max_p}
__device__ float g_part[BC * SPLIT * 5];

__global__ __launch_bounds__(NTHREADS)
void partial_kernel(const float4* __restrict__ no,
                    const float4* __restrict__ tg,
                    const float4* __restrict__ mp)
{
    const int cls  = blockIdx.x / SPLIT;
    const int part = blockIdx.x % SPLIT;
    const long base = (long)cls * HW4 + (long)part * CHUNK4;

    float s_d2t = 0.f, s_d2 = 0.f, s_t = 0.f;
    float mxt = -1e30f, mxp = -1e30f;

    for (int i = threadIdx.x; i < CHUNK4; i += NTHREADS) {
        float4 t = tg[base + i];
        float4 n = no[base + i];
        float4 p = mp[base + i];

        float d;
        d = t.x - n.x; float d2x = d * d;
        d = t.y - n.y; float d2y = d * d;
        d = t.z - n.z; float d2z = d * d;
        d = t.w - n.w; float d2w = d * d;

        s_d2  += d2x + d2y + d2z + d2w;
        s_d2t += d2x * t.x + d2y * t.y + d2z * t.z + d2w * t.w;
        s_t   += t.x + t.y + t.z + t.w;
        mxt = fmaxf(mxt, fmaxf(fmaxf(t.x, t.y), fmaxf(t.z, t.w)));
        mxp = fmaxf(mxp, fmaxf(fmaxf(p.x, p.y), fmaxf(p.z, p.w)));
    }

    // warp reduce
    #pragma unroll
    for (int off = 16; off > 0; off >>= 1) {
        s_d2t += __shfl_xor_sync(0xffffffff, s_d2t, off);
        s_d2  += __shfl_xor_sync(0xffffffff, s_d2,  off);
        s_t   += __shfl_xor_sync(0xffffffff, s_t,   off);
        mxt = fmaxf(mxt, __shfl_xor_sync(0xffffffff, mxt, off));
        mxp = fmaxf(mxp, __shfl_xor_sync(0xffffffff, mxp, off));
    }

    __shared__ float sh[NTHREADS / 32][5];
    const int wid = threadIdx.x >> 5;
    const int lid = threadIdx.x & 31;
    if (lid == 0) {
        sh[wid][0] = s_d2t; sh[wid][1] = s_d2; sh[wid][2] = s_t;
        sh[wid][3] = mxt;   sh[wid][4] = mxp;
    }
    __syncthreads();

    if (wid == 0) {
        const int nw = NTHREADS / 32;
        float v0 = (lid < nw) ? sh[lid][0] : 0.f;
        float v1 = (lid < nw) ? sh[lid][1] : 0.f;
        float v2 = (lid < nw) ? sh[lid][2] : 0.f;
        float v3 = (lid < nw) ? sh[lid][3] : -1e30f;
        float v4 = (lid < nw) ? sh[lid][4] : -1e30f;
        #pragma unroll
        for (int off = 4; off > 0; off >>= 1) {
            v0 += __shfl_xor_sync(0xffffffff, v0, off);
            v1 += __shfl_xor_sync(0xffffffff, v1, off);
            v2 += __shfl_xor_sync(0xffffffff, v2, off);
            v3 = fmaxf(v3, __shfl_xor_sync(0xffffffff, v3, off));
            v4 = fmaxf(v4, __shfl_xor_sync(0xffffffff, v4, off));
        }
        if (lid == 0) {
            float* dst = &g_part[(long)blockIdx.x * 5];
            dst[0] = v0; dst[1] = v1; dst[2] = v2; dst[3] = v3; dst[4] = v4;
        }
    }
}

__global__ __launch_bounds__(128)
void final_kernel(float* __restrict__ out)
{
    const int cls = threadIdx.x;   // 0..127

    float s_d2t = 0.f, s_d2 = 0.f, s_t = 0.f;
    float mxt = -1e30f, mxp = -1e30f;
    #pragma unroll
    for (int j = 0; j < SPLIT; j++) {
        const float* src = &g_part[(long)(cls * SPLIT + j) * 5];
        s_d2t += src[0];
        s_d2  += src[1];
        s_t   += src[2];
        mxt = fmaxf(mxt, src[3]);
        mxp = fmaxf(mxp, src[4]);
    }

    float m1 = s_d2t;
    float m2 = s_d2 - s_d2t;
    float d1 = s_t;
    float d2 = (float)HW - s_t;
    float loss = ALPHA * m1 / (d1 + SMOOTH) + (1.0f - ALPHA) * m2 / (d2 + SMOOTH);

    bool active = !((mxt == 0.0f) && (mxp == 0.0f));
    float l = active ? loss : 0.0f;

    __shared__ float losses[BC];
    losses[cls] = l;
    __syncthreads();

    __shared__ float imgl[B_DIM];
    if (cls < B_DIM) {
        float s = 0.f;
        float cnt = 0.f;
        #pragma unroll
        for (int c = 0; c < C_DIM; c++) {
            float v = losses[cls * C_DIM + c];
            s += v;
            if (v != 0.0f) cnt += 1.0f;
        }
        imgl[cls] = s / cnt;
    }
    __syncthreads();

    if (cls == 0) {
        float s = 0.f;
        #pragma unroll
        for (int b = 0; b < B_DIM; b++) s += imgl[b];
        out[0] = s / (float)B_DIM;
    }
}

extern "C" void kernel_launch(void* const* d_in, const int* in_sizes, int n_in,
                              void* d_out, int out_size)
{
    const float4* no = (const float4*)d_in[0];   // net_out
    const float4* tg = (const float4*)d_in[1];   // target
    const float4* mp = (const float4*)d_in[2];   // max_positiones

    partial_kernel<<<BC * SPLIT, NTHREADS>>>(no, tg, mp);
    final_kernel<<<1, 128>>>((float*)d_out);
}

// round 2
// speedup vs baseline: 1.1853x; 1.1853x over previous
#include <cuda_runtime.h>

#define BC      128          // B*C = 8*16
#define B_DIM   8
#define C_DIM   16
#define HW      147456       // 384*384
#define HW4     36864        // HW/4
#define SPLIT   12
#define CHUNK4  (HW4 / SPLIT)   // 3072
#define NTHREADS 256
#define NBLOCKS (BC * SPLIT)

#define ALPHA   0.05f
#define SMOOTH  1e-6f

// scratch: [NBLOCKS][5] partials: {sum_d2t, sum_d2, sum_t, max_t, max_p}
__device__ float g_part[NBLOCKS * 5];
__device__ int   g_count = 0;

__global__ __launch_bounds__(NTHREADS)
void fused_kernel(const float4* __restrict__ no,
                  const float4* __restrict__ tg,
                  const float4* __restrict__ mp,
                  float* __restrict__ out)
{
    const int cls  = blockIdx.x / SPLIT;
    const int part = blockIdx.x % SPLIT;
    const long base = (long)cls * HW4 + (long)part * CHUNK4;

    const int wid = threadIdx.x >> 5;
    const int lid = threadIdx.x & 31;
    const int NW  = NTHREADS / 32;

    float s_d2t = 0.f, s_d2 = 0.f, s_t = 0.f;
    float mxt = -1e30f;

    // ---- pass 1: target + net_out only ----
    for (int i = threadIdx.x; i < CHUNK4; i += NTHREADS) {
        float4 t = tg[base + i];
        float4 n = no[base + i];

        float d;
        d = t.x - n.x; float d2x = d * d;
        d = t.y - n.y; float d2y = d * d;
        d = t.z - n.z; float d2z = d * d;
        d = t.w - n.w; float d2w = d * d;

        s_d2  += d2x + d2y + d2z + d2w;
        s_d2t += d2x * t.x + d2y * t.y + d2z * t.z + d2w * t.w;
        s_t   += t.x + t.y + t.z + t.w;
        mxt = fmaxf(mxt, fmaxf(fmaxf(t.x, t.y), fmaxf(t.z, t.w)));
    }

    #pragma unroll
    for (int off = 16; off > 0; off >>= 1) {
        s_d2t += __shfl_xor_sync(0xffffffff, s_d2t, off);
        s_d2  += __shfl_xor_sync(0xffffffff, s_d2,  off);
        s_t   += __shfl_xor_sync(0xffffffff, s_t,   off);
        mxt = fmaxf(mxt, __shfl_xor_sync(0xffffffff, mxt, off));
    }

    __shared__ float sh[NTHREADS / 32][4];
    __shared__ float sh_blkmax;
    if (lid == 0) {
        sh[wid][0] = s_d2t; sh[wid][1] = s_d2; sh[wid][2] = s_t; sh[wid][3] = mxt;
    }
    __syncthreads();

    // block-level reduce (warp 0) and broadcast block max(t)
    if (wid == 0) {
        float v0 = (lid < NW) ? sh[lid][0] : 0.f;
        float v1 = (lid < NW) ? sh[lid][1] : 0.f;
        float v2 = (lid < NW) ? sh[lid][2] : 0.f;
        float v3 = (lid < NW) ? sh[lid][3] : -1e30f;
        #pragma unroll
        for (int off = 4; off > 0; off >>= 1) {
            v0 += __shfl_xor_sync(0xffffffff, v0, off);
            v1 += __shfl_xor_sync(0xffffffff, v1, off);
            v2 += __shfl_xor_sync(0xffffffff, v2, off);
            v3 = fmaxf(v3, __shfl_xor_sync(0xffffffff, v3, off));
        }
        if (lid == 0) {
            sh[0][0] = v0; sh[0][1] = v1; sh[0][2] = v2;
            sh_blkmax = v3;
        }
    }
    __syncthreads();

    // ---- pass 2 (rare): only if this block's target chunk is all-zero does
    // max_positiones matter for the active-class test. If any t > 0 in this
    // chunk the class is active regardless of mp, and this block's mxp is
    // never consulted (global max_t > 0).
    float mxp = -1e30f;
    if (sh_blkmax == 0.0f) {
        for (int i = threadIdx.x; i < CHUNK4; i += NTHREADS) {
            float4 p = mp[base + i];
            mxp = fmaxf(mxp, fmaxf(fmaxf(p.x, p.y), fmaxf(p.z, p.w)));
        }
        #pragma unroll
        for (int off = 16; off > 0; off >>= 1)
            mxp = fmaxf(mxp, __shfl_xor_sync(0xffffffff, mxp, off));
        __shared__ float shp[NTHREADS / 32];
        if (lid == 0) shp[wid] = mxp;
        __syncthreads();
        if (wid == 0) {
            float v = (lid < NW) ? shp[lid] : -1e30f;
            #pragma unroll
            for (int off = 4; off > 0; off >>= 1)
                v = fmaxf(v, __shfl_xor_sync(0xffffffff, v, off));
            mxp = v;
        }
    }

    __shared__ bool s_last;
    if (threadIdx.x == 0) {
        float* dst = &g_part[(long)blockIdx.x * 5];
        dst[0] = sh[0][0]; dst[1] = sh[0][1]; dst[2] = sh[0][2];
        dst[3] = sh_blkmax; dst[4] = mxp;
        __threadfence();
        int old = atomicAdd(&g_count, 1);
        s_last = (old == NBLOCKS - 1);
    }
    __syncthreads();

    if (!s_last) return;

    // ---- fused epilogue: last block reduces all partials ----
    __shared__ float losses[BC];
    __shared__ float imgl[B_DIM];

    if (threadIdx.x < BC) {
        const int c = threadIdx.x;
        float a_d2t = 0.f, a_d2 = 0.f, a_t = 0.f;
        float a_mt = -1e30f, a_mp = -1e30f;
        #pragma unroll
        for (int j = 0; j < SPLIT; j++) {
            const float* src = &g_part[(long)(c * SPLIT + j) * 5];
            a_d2t += __ldcg(src + 0);
            a_d2  += __ldcg(src + 1);
            a_t   += __ldcg(src + 2);
            a_mt = fmaxf(a_mt, __ldcg(src + 3));
            a_mp = fmaxf(a_mp, __ldcg(src + 4));
        }
        float m1 = a_d2t;
        float m2 = a_d2 - a_d2t;
        float d1 = a_t;
        float d2 = (float)HW - a_t;
        float loss = ALPHA * m1 / (d1 + SMOOTH) + (1.0f - ALPHA) * m2 / (d2 + SMOOTH);
        bool active = !((a_mt == 0.0f) && (a_mp == 0.0f));
        losses[c] = active ? loss : 0.0f;
    }
    __syncthreads();

    if (threadIdx.x < B_DIM) {
        float s = 0.f, cnt = 0.f;
        #pragma unroll
        for (int c = 0; c < C_DIM; c++) {
            float v = losses[threadIdx.x * C_DIM + c];
            s += v;
            if (v != 0.0f) cnt += 1.0f;
        }
        imgl[threadIdx.x] = s / cnt;
    }
    __syncthreads();

    if (threadIdx.x == 0) {
        float s = 0.f;
        #pragma unroll
        for (int b = 0; b < B_DIM; b++) s += imgl[b];
        out[0] = s / (float)B_DIM;
        g_count = 0;   // reset for next graph replay (deterministic)
    }
}

extern "C" void kernel_launch(void* const* d_in, const int* in_sizes, int n_in,
                              void* d_out, int out_size)
{
    const float4* no = (const float4*)d_in[0];   // net_out
    const float4* tg = (const float4*)d_in[1];   // target
    const float4* mp = (const float4*)d_in[2];   // max_positiones

    fused_kernel<<<NBLOCKS, NTHREADS>>>(no, tg, mp, (float*)d_out);
}

// round 3
// speedup vs baseline: 1.2993x; 1.0962x over previous
#include <cuda_runtime.h>

#define BC      128          // B*C = 8*16
#define B_DIM   8
#define C_DIM   16
#define HW      147456       // 384*384
#define HW4     36864        // HW/4
#define SPLIT   12
#define CHUNK4  (HW4 / SPLIT)   // 3072
#define NTHREADS 256
#define NBLOCKS (BC * SPLIT)
#define PER_THR (CHUNK4 / NTHREADS)  // 12
#define UNROLL  4

#define ALPHA   0.05f
#define SMOOTH  1e-6f

// scratch: [NBLOCKS][5] partials: {sum_d2t, sum_d2, sum_t, max_t, max_p}
__device__ float g_part[NBLOCKS * 5];
__device__ int   g_count = 0;

__global__ __launch_bounds__(NTHREADS)
void fused_kernel(const float4* __restrict__ no,
                  const float4* __restrict__ tg,
                  const float4* __restrict__ mp,
                  float* __restrict__ out)
{
    const int cls  = blockIdx.x / SPLIT;
    const int part = blockIdx.x % SPLIT;
    const long base = (long)cls * HW4 + (long)part * CHUNK4;

    const int wid = threadIdx.x >> 5;
    const int lid = threadIdx.x & 31;
    const int NW  = NTHREADS / 32;

    float s_d2t = 0.f, s_d2 = 0.f, s_t = 0.f;
    float mxt = -1e30f;

    const float4* tp = tg + base + threadIdx.x;
    const float4* np = no + base + threadIdx.x;

    // ---- pass 1: target + net_out, batched loads for MLP=8 ----
    #pragma unroll
    for (int k = 0; k < PER_THR; k += UNROLL) {
        float4 t[UNROLL], n[UNROLL];
        #pragma unroll
        for (int u = 0; u < UNROLL; u++) t[u] = __ldcs(tp + (k + u) * NTHREADS);
        #pragma unroll
        for (int u = 0; u < UNROLL; u++) n[u] = __ldcs(np + (k + u) * NTHREADS);

        #pragma unroll
        for (int u = 0; u < UNROLL; u++) {
            float d;
            d = t[u].x - n[u].x; float d2x = d * d;
            d = t[u].y - n[u].y; float d2y = d * d;
            d = t[u].z - n[u].z; float d2z = d * d;
            d = t[u].w - n[u].w; float d2w = d * d;

            s_d2  += d2x + d2y + d2z + d2w;
            s_d2t += d2x * t[u].x + d2y * t[u].y + d2z * t[u].z + d2w * t[u].w;
            s_t   += t[u].x + t[u].y + t[u].z + t[u].w;
            mxt = fmaxf(mxt, fmaxf(fmaxf(t[u].x, t[u].y), fmaxf(t[u].z, t[u].w)));
        }
    }

    #pragma unroll
    for (int off = 16; off > 0; off >>= 1) {
        s_d2t += __shfl_xor_sync(0xffffffff, s_d2t, off);
        s_d2  += __shfl_xor_sync(0xffffffff, s_d2,  off);
        s_t   += __shfl_xor_sync(0xffffffff, s_t,   off);
        mxt = fmaxf(mxt, __shfl_xor_sync(0xffffffff, mxt, off));
    }

    __shared__ float sh[NTHREADS / 32][4];
    __shared__ float sh_blkmax;
    if (lid == 0) {
        sh[wid][0] = s_d2t; sh[wid][1] = s_d2; sh[wid][2] = s_t; sh[wid][3] = mxt;
    }
    __syncthreads();

    if (wid == 0) {
        float v0 = (lid < NW) ? sh[lid][0] : 0.f;
        float v1 = (lid < NW) ? sh[lid][1] : 0.f;
        float v2 = (lid < NW) ? sh[lid][2] : 0.f;
        float v3 = (lid < NW) ? sh[lid][3] : -1e30f;
        #pragma unroll
        for (int off = 4; off > 0; off >>= 1) {
            v0 += __shfl_xor_sync(0xffffffff, v0, off);
            v1 += __shfl_xor_sync(0xffffffff, v1, off);
            v2 += __shfl_xor_sync(0xffffffff, v2, off);
            v3 = fmaxf(v3, __shfl_xor_sync(0xffffffff, v3, off));
        }
        if (lid == 0) {
            sh[0][0] = v0; sh[0][1] = v1; sh[0][2] = v2;
            sh_blkmax = v3;
        }
    }
    __syncthreads();

    // ---- pass 2 (rare): mp only matters if this block's target chunk is
    // all-zero (if any t>0 the class is active and global max_t>0, so this
    // block's mxp is never consulted).
    float mxp = -1e30f;
    if (sh_blkmax == 0.0f) {
        const float4* pp = mp + base + threadIdx.x;
        #pragma unroll
        for (int k = 0; k < PER_THR; k++) {
            float4 p = __ldcs(pp + k * NTHREADS);
            mxp = fmaxf(mxp, fmaxf(fmaxf(p.x, p.y), fmaxf(p.z, p.w)));
        }
        #pragma unroll
        for (int off = 16; off > 0; off >>= 1)
            mxp = fmaxf(mxp, __shfl_xor_sync(0xffffffff, mxp, off));
        __shared__ float shp[NTHREADS / 32];
        if (lid == 0) shp[wid] = mxp;
        __syncthreads();
        if (wid == 0) {
            float v = (lid < NW) ? shp[lid] : -1e30f;
            #pragma unroll
            for (int off = 4; off > 0; off >>= 1)
                v = fmaxf(v, __shfl_xor_sync(0xffffffff, v, off));
            mxp = v;
        }
    }

    __shared__ bool s_last;
    if (threadIdx.x == 0) {
        float* dst = &g_part[(long)blockIdx.x * 5];
        dst[0] = sh[0][0]; dst[1] = sh[0][1]; dst[2] = sh[0][2];
        dst[3] = sh_blkmax; dst[4] = mxp;
        __threadfence();
        int old = atomicAdd(&g_count, 1);
        s_last = (old == NBLOCKS - 1);
    }
    __syncthreads();

    if (!s_last) return;

    // ---- fused epilogue: last block reduces all partials ----
    __shared__ float losses[BC];
    __shared__ float imgl[B_DIM];

    if (threadIdx.x < BC) {
        const int c = threadIdx.x;
        float a_d2t = 0.f, a_d2 = 0.f, a_t = 0.f;
        float a_mt = -1e30f, a_mp = -1e30f;
        #pragma unroll
        for (int j = 0; j < SPLIT; j++) {
            const float* src = &g_part[(long)(c * SPLIT + j) * 5];
            a_d2t += __ldcg(src + 0);
            a_d2  += __ldcg(src + 1);
            a_t   += __ldcg(src + 2);
            a_mt = fmaxf(a_mt, __ldcg(src + 3));
            a_mp = fmaxf(a_mp, __ldcg(src + 4));
        }
        float m1 = a_d2t;
        float m2 = a_d2 - a_d2t;
        float d1 = a_t;
        float d2 = (float)HW - a_t;
        float loss = ALPHA * m1 / (d1 + SMOOTH) + (1.0f - ALPHA) * m2 / (d2 + SMOOTH);
        bool active = !((a_mt == 0.0f) && (a_mp == 0.0f));
        losses[c] = active ? loss : 0.0f;
    }
    __syncthreads();

    if (threadIdx.x < B_DIM) {
        float s = 0.f, cnt = 0.f;
        #pragma unroll
        for (int c = 0; c < C_DIM; c++) {
            float v = losses[threadIdx.x * C_DIM + c];
            s += v;
            if (v != 0.0f) cnt += 1.0f;
        }
        imgl[threadIdx.x] = s / cnt;
    }
    __syncthreads();

    if (threadIdx.x == 0) {
        float s = 0.f;
        #pragma unroll
        for (int b = 0; b < B_DIM; b++) s += imgl[b];
        out[0] = s / (float)B_DIM;
        g_count = 0;   // reset for next graph replay (deterministic)
    }
}

extern "C" void kernel_launch(void* const* d_in, const int* in_sizes, int n_in,
                              void* d_out, int out_size)
{
    const float4* no = (const float4*)d_in[0];   // net_out
    const float4* tg = (const float4*)d_in[1];   // target
    const float4* mp = (const float4*)d_in[2];   // max_positiones

    fused_kernel<<<NBLOCKS, NTHREADS>>>(no, tg, mp, (float*)d_out);
}